// round 2
// baseline (speedup 1.0000x reference)
#include <cuda_runtime.h>

#define Bsz 256
#define Tt  200
#define Dd  128
#define Hh  256
#define Oo  128
#define Mm  64
#define RPB 4            // batch rows per block
#define NBLK (Bsz/RPB)   // 64 CTAs
#define NTHR 256

// Transposed / interleaved weights in device globals (no allocs allowed).
// g_WgT: [k][h] -> float4 = (Wi[h][k], Wf[h][k], Wo[h][k], Wc[h][k]); k in [0,320), h in [0,256)
__device__ __align__(16) float g_WgT[320 * 256 * 4];
__device__ float g_WqT[384 * 64];     // [k][m] = Wq[m][k]
__device__ float g_WfcT[256 * 128];   // [h][o] = Wfc[o][h]
__device__ float g_wzd[128];          // diag(Wz)
__device__ float g_wzpd[128];         // diag(Wzp)

__global__ void prep_kernel(const float* __restrict__ Wz,  const float* __restrict__ Wzp,
                            const float* __restrict__ Wq,  const float* __restrict__ Wi,
                            const float* __restrict__ Wf,  const float* __restrict__ Wo,
                            const float* __restrict__ Wc,  const float* __restrict__ Wfc)
{
    int idx = blockIdx.x * blockDim.x + threadIdx.x;   // 0 .. 81919
    if (idx < 320 * 256) {
        int k = idx >> 8, h = idx & 255;
        float4 w;
        w.x = Wi[h * 320 + k];
        w.y = Wf[h * 320 + k];
        w.z = Wo[h * 320 + k];
        w.w = Wc[h * 320 + k];
        reinterpret_cast<float4*>(g_WgT)[idx] = w;     // [k*256 + h]
    }
    if (idx < 384 * 64) {
        int k = idx >> 6, m = idx & 63;
        g_WqT[idx] = Wq[m * 384 + k];
    }
    if (idx < 256 * 128) {
        int h = idx >> 7, o = idx & 127;
        g_WfcT[idx] = Wfc[o * 256 + h];
    }
    if (idx < 128) {
        g_wzd[idx]  = Wz[idx * 128 + idx];
        g_wzpd[idx] = Wzp[idx * 128 + idx];
    }
}

__device__ __forceinline__ float fast_sigmoid(float x) {
    return 1.0f / (1.0f + __expf(-x));
}
__device__ __forceinline__ float fast_tanh(float x) {
    // tanh(x) = 1 - 2/(exp(2x)+1); saturates correctly at +-inf with __expf
    return 1.0f - 2.0f / (__expf(2.0f * x) + 1.0f);
}

__global__ __launch_bounds__(NTHR) void lgnet_kernel(
    const float* __restrict__ inp,    // [B,6,T,D]
    const float* __restrict__ xmean,  // [B,T,D]
    const float* __restrict__ bz,  const float* __restrict__ bzp,
    const float* __restrict__ bq,
    const float* __restrict__ bi,  const float* __restrict__ bf,
    const float* __restrict__ bo,  const float* __restrict__ bc,
    const float* __restrict__ bfc,
    float* __restrict__ out)          // [B,T,O]
{
    __shared__ __align__(16) float s_u[RPB][384];    // [z | zp | x_i]
    __shared__ __align__(16) float s_comb[RPB][320]; // [ls | h]
    __shared__ float s_wzd[128], s_bz[128], s_wzpd[128], s_bzp[128];
    __shared__ float s_bq[64], s_bfc[128];

    const int tid = threadIdx.x;
    const int b0  = blockIdx.x * RPB;

    if (tid < 128) {
        s_wzd[tid]  = g_wzd[tid];   s_bz[tid]  = bz[tid];
        s_wzpd[tid] = g_wzpd[tid];  s_bzp[tid] = bzp[tid];
        s_bfc[tid]  = bfc[tid];
    }
    if (tid < 64) s_bq[tid] = bq[tid];

    // gate biases for h = tid (thread-stationary)
    const float bi_r = bi[tid], bf_r = bf[tid], bo_r = bo[tid], bc_r = bc[tid];

    float c_reg[RPB];
#pragma unroll
    for (int r = 0; r < RPB; r++) c_reg[r] = 0.0f;

    // init: comb h-part = 0 (h0 = 0), u x_i part = bfc (x_i_0 = 0@Wfc + bfc)
#pragma unroll
    for (int r = 0; r < RPB; r++) s_comb[r][64 + tid] = 0.0f;
    for (int e = tid; e < RPB * 128; e += NTHR)
        s_u[e >> 7][256 + (e & 127)] = bfc[e & 127];
    __syncthreads();

    const float4* __restrict__ WgT4 = reinterpret_cast<const float4*>(g_WgT);

    for (int t = 0; t < Tt; t++) {
        // ---------- Phase A: z, zp (elementwise, diag filters) ----------
        for (int e = tid; e < RPB * 128; e += NTHR) {
            int r = e >> 7, j = e & 127;
            long base = ((long)(b0 + r) * 6 * Tt + t) * (long)Dd + j;
            const long cs = (long)Tt * Dd;
            float x   = inp[base];
            float xl  = inp[base + 1 * cs];
            float mk  = inp[base + 2 * cs];
            float dl  = inp[base + 3 * cs];
            float xlb = inp[base + 4 * cs];
            float dlb = inp[base + 5 * cs];
            float xm  = xmean[((long)(b0 + r) * Tt + t) * (long)Dd + j];

            float dz  = __expf(-fmaxf(fmaf(dl,  s_wzd[j],  s_bz[j]),  0.0f));
            float dzp = __expf(-fmaxf(fmaf(dlb, s_wzpd[j], s_bzp[j]), 0.0f));
            float z   = mk * x + (1.0f - mk) * (dz  * xl  + (1.0f - dz)  * xm);
            float zp  = mk * x + (1.0f - mk) * (dzp * xlb + (1.0f - dzp) * xm);
            s_u[r][j]       = z;
            s_u[r][128 + j] = zp;
        }
        __syncthreads();

        // ---------- Phase B: ls = [z,zp,x_i] @ Wq^T + bq -> comb[:,0:64] ----------
        {
            int r = tid >> 6, m = tid & 63;   // RPB*64 == NTHR
            float acc = s_bq[m];
#pragma unroll 8
            for (int k = 0; k < 384; k++)
                acc = fmaf(s_u[r][k], g_WqT[k * 64 + m], acc);
            s_comb[r][m] = acc;
        }
        __syncthreads();

        // ---------- Phase C: 4 gates, thread owns h = tid for all RPB rows ----------
        float ai[RPB], af[RPB], ao[RPB], ac[RPB];
#pragma unroll
        for (int r = 0; r < RPB; r++) { ai[r] = bi_r; af[r] = bf_r; ao[r] = bo_r; ac[r] = bc_r; }

#pragma unroll 2
        for (int k0 = 0; k0 < 320; k0 += 4) {
            float4 w0 = WgT4[(k0 + 0) * 256 + tid];
            float4 w1 = WgT4[(k0 + 1) * 256 + tid];
            float4 w2 = WgT4[(k0 + 2) * 256 + tid];
            float4 w3 = WgT4[(k0 + 3) * 256 + tid];
#pragma unroll
            for (int r = 0; r < RPB; r++) {
                float4 cb = *reinterpret_cast<const float4*>(&s_comb[r][k0]);
                ai[r] = fmaf(cb.x, w0.x, ai[r]); af[r] = fmaf(cb.x, w0.y, af[r]);
                ao[r] = fmaf(cb.x, w0.z, ao[r]); ac[r] = fmaf(cb.x, w0.w, ac[r]);
                ai[r] = fmaf(cb.y, w1.x, ai[r]); af[r] = fmaf(cb.y, w1.y, af[r]);
                ao[r] = fmaf(cb.y, w1.z, ao[r]); ac[r] = fmaf(cb.y, w1.w, ac[r]);
                ai[r] = fmaf(cb.z, w2.x, ai[r]); af[r] = fmaf(cb.z, w2.y, af[r]);
                ao[r] = fmaf(cb.z, w2.z, ao[r]); ac[r] = fmaf(cb.z, w2.w, ac[r]);
                ai[r] = fmaf(cb.w, w3.x, ai[r]); af[r] = fmaf(cb.w, w3.y, af[r]);
                ao[r] = fmaf(cb.w, w3.z, ao[r]); ac[r] = fmaf(cb.w, w3.w, ac[r]);
            }
        }

        float hreg[RPB];
#pragma unroll
        for (int r = 0; r < RPB; r++) {
            float ig = fast_sigmoid(ai[r]);
            float fg = fast_sigmoid(af[r]);
            float og = fast_sigmoid(ao[r]);
            float ct = fast_tanh(ac[r]);
            c_reg[r] = fg * c_reg[r] + ig * ct;
            hreg[r]  = og * fast_tanh(c_reg[r]);
        }
        __syncthreads();   // all comb reads complete before overwriting h-part
#pragma unroll
        for (int r = 0; r < RPB; r++) s_comb[r][64 + tid] = hreg[r];
        __syncthreads();

        // ---------- Phase E: out = h_new @ Wfc^T + bfc; also x_i for t+1 ----------
        for (int e = tid; e < RPB * 128; e += NTHR) {
            int r = e >> 7, o = e & 127;
            float acc = s_bfc[o];
#pragma unroll 8
            for (int h = 0; h < 256; h++)
                acc = fmaf(s_comb[r][64 + h], g_WfcT[h * 128 + o], acc);
            out[((long)(b0 + r) * Tt + t) * (long)Oo + o] = acc;
            s_u[r][256 + o] = acc;   // disjoint from next Phase A's writes; read after next sync
        }
        // no sync needed: next-A writes s_u[0:256) (disjoint), next-B reads after sync-after-A
    }
}

extern "C" void kernel_launch(void* const* d_in, const int* in_sizes, int n_in,
                              void* d_out, int out_size)
{
    const float* inp   = (const float*)d_in[0];
    const float* xmean = (const float*)d_in[1];
    const float* Wz    = (const float*)d_in[2];
    const float* bz    = (const float*)d_in[3];
    const float* Wzp   = (const float*)d_in[4];
    const float* bzp   = (const float*)d_in[5];
    const float* Wq    = (const float*)d_in[6];
    const float* bq    = (const float*)d_in[7];
    const float* Wi    = (const float*)d_in[8];
    const float* bi    = (const float*)d_in[9];
    const float* Wf    = (const float*)d_in[10];
    const float* bf    = (const float*)d_in[11];
    const float* Wo    = (const float*)d_in[12];
    const float* bo    = (const float*)d_in[13];
    const float* Wc    = (const float*)d_in[14];
    const float* bc    = (const float*)d_in[15];
    const float* Wfc   = (const float*)d_in[16];
    const float* bfc   = (const float*)d_in[17];
    float* out = (float*)d_out;

    prep_kernel<<<320, 256>>>(Wz, Wzp, Wq, Wi, Wf, Wo, Wc, Wfc);
    lgnet_kernel<<<NBLK, NTHR>>>(inp, xmean, bz, bzp, bq, bi, bf, bo, bc, bfc, out);
}

// round 3
// speedup vs baseline: 1.6823x; 1.6823x over previous
#include <cuda_runtime.h>

#define Bsz 256
#define Tt  200
#define Dd  128
#define Hh  256
#define Oo  128
#define RPB 4            // batch rows per block
#define NBLK (Bsz/RPB)   // 64 CTAs
#define NTHR 256

// Transposed / interleaved weights in device globals (no allocs allowed).
// g_WgT: [k][h] -> float4 = (Wi[h][k], Wf[h][k], Wo[h][k], Wc[h][k]); k in [0,320), h in [0,256)
// Padded to 336 k's (zero) so the prefetch pipeline can read past k=319 safely.
__device__ __align__(16) float g_WgT[336 * 256 * 4];
__device__ float g_WqT[384 * 64];     // [k][m] = Wq[m][k]
__device__ float g_WfcT[256 * 128];   // [h][o] = Wfc[o][h]
__device__ float g_wzd[128];          // diag(Wz)
__device__ float g_wzpd[128];         // diag(Wzp)

__global__ void prep_kernel(const float* __restrict__ Wz,  const float* __restrict__ Wzp,
                            const float* __restrict__ Wq,  const float* __restrict__ Wi,
                            const float* __restrict__ Wf,  const float* __restrict__ Wo,
                            const float* __restrict__ Wc,  const float* __restrict__ Wfc)
{
    int idx = blockIdx.x * blockDim.x + threadIdx.x;   // 0 .. 81919
    if (idx < 320 * 256) {
        int k = idx >> 8, h = idx & 255;
        float4 w;
        w.x = Wi[h * 320 + k];
        w.y = Wf[h * 320 + k];
        w.z = Wo[h * 320 + k];
        w.w = Wc[h * 320 + k];
        reinterpret_cast<float4*>(g_WgT)[idx] = w;     // [k*256 + h]
    }
    if (idx < 384 * 64) {
        int k = idx >> 6, m = idx & 63;
        g_WqT[idx] = Wq[m * 384 + k];
    }
    if (idx < 256 * 128) {
        int h = idx >> 7, o = idx & 127;
        g_WfcT[idx] = Wfc[o * 256 + h];
    }
    if (idx < 128) {
        g_wzd[idx]  = Wz[idx * 128 + idx];
        g_wzpd[idx] = Wzp[idx * 128 + idx];
    }
}

__device__ __forceinline__ float fast_sigmoid(float x) {
    return 1.0f / (1.0f + __expf(-x));
}
__device__ __forceinline__ float fast_tanh(float x) {
    return 1.0f - 2.0f / (__expf(2.0f * x) + 1.0f);
}

// ---- packed f32x2 helpers (Blackwell FFMA2: 2x fp32 throughput) ----
__device__ __forceinline__ unsigned long long pack2(float lo, float hi) {
    unsigned long long r;
    asm("mov.b64 %0, {%1, %2};" : "=l"(r) : "f"(lo), "f"(hi));
    return r;
}
__device__ __forceinline__ void unpack2(unsigned long long v, float& lo, float& hi) {
    asm("mov.b64 {%0, %1}, %2;" : "=f"(lo), "=f"(hi) : "l"(v));
}
__device__ __forceinline__ void fma2(unsigned long long& d, unsigned long long a, unsigned long long b) {
    asm("fma.rn.f32x2 %0, %1, %2, %0;" : "+l"(d) : "l"(a), "l"(b));
}
// streaming (evict-first) 16B load as two packed u64 lanes
__device__ __forceinline__ ulonglong2 ldcs_v2(const ulonglong2* p) {
    ulonglong2 v;
    asm("ld.global.cs.v2.b64 {%0, %1}, [%2];" : "=l"(v.x), "=l"(v.y) : "l"(p));
    return v;
}

__global__ __launch_bounds__(NTHR) void lgnet_kernel(
    const float* __restrict__ inp,    // [B,6,T,D]
    const float* __restrict__ xmean,  // [B,T,D]
    const float* __restrict__ bz,  const float* __restrict__ bzp,
    const float* __restrict__ bq,
    const float* __restrict__ bi,  const float* __restrict__ bf,
    const float* __restrict__ bo,  const float* __restrict__ bc,
    const float* __restrict__ bfc,
    float* __restrict__ out)          // [B,T,O]
{
    __shared__ __align__(16) float  s_u[RPB][384];       // [z | zp | x_i]  (scalar)
    __shared__ __align__(16) float2 s_comb2[RPB][320];   // [ls | h], each entry duplicated (v,v)
    __shared__ __align__(16) float  s_partB[RPB][64][4]; // Wq partials per k-slice
    __shared__ __align__(16) float  s_partE[RPB][128][2];// Wfc partials per h-slice
    __shared__ float s_wzd[128], s_bz[128], s_wzpd[128], s_bzp[128];
    __shared__ float s_bq[64], s_bfc[128];

    const int tid = threadIdx.x;
    const int b0  = blockIdx.x * RPB;

    if (tid < 128) {
        s_wzd[tid]  = g_wzd[tid];   s_bz[tid]  = bz[tid];
        s_wzpd[tid] = g_wzpd[tid];  s_bzp[tid] = bzp[tid];
        s_bfc[tid]  = bfc[tid];
    }
    if (tid < 64) s_bq[tid] = bq[tid];

    // gate biases for h = tid, packed (i,f) and (o,c)
    const unsigned long long bias_if = pack2(bi[tid], bf[tid]);
    const unsigned long long bias_oc = pack2(bo[tid], bc[tid]);

    float c_reg[RPB];
#pragma unroll
    for (int r = 0; r < RPB; r++) c_reg[r] = 0.0f;

    // init: comb h-part = 0 (h0 = 0), u x_i part = bfc (x_i_0 = 0@Wfc + bfc)
#pragma unroll
    for (int r = 0; r < RPB; r++) s_comb2[r][64 + tid] = make_float2(0.0f, 0.0f);
    for (int e = tid; e < RPB * 128; e += NTHR)
        s_u[e >> 7][256 + (e & 127)] = bfc[e & 127];
    __syncthreads();

    const ulonglong2* __restrict__ wg = reinterpret_cast<const ulonglong2*>(g_WgT) + tid;

    for (int t = 0; t < Tt; t++) {
        // ---------- Phase A: z, zp (elementwise, diag filters) ----------
        for (int e = tid; e < RPB * 128; e += NTHR) {
            int r = e >> 7, j = e & 127;
            long base = ((long)(b0 + r) * 6 * Tt + t) * (long)Dd + j;
            const long cs = (long)Tt * Dd;
            float x   = __ldcs(inp + base);
            float xl  = __ldcs(inp + base + 1 * cs);
            float mk  = __ldcs(inp + base + 2 * cs);
            float dl  = __ldcs(inp + base + 3 * cs);
            float xlb = __ldcs(inp + base + 4 * cs);
            float dlb = __ldcs(inp + base + 5 * cs);
            float xm  = __ldcs(xmean + ((long)(b0 + r) * Tt + t) * (long)Dd + j);

            float dz  = __expf(-fmaxf(fmaf(dl,  s_wzd[j],  s_bz[j]),  0.0f));
            float dzp = __expf(-fmaxf(fmaf(dlb, s_wzpd[j], s_bzp[j]), 0.0f));
            float z   = mk * x + (1.0f - mk) * (dz  * xl  + (1.0f - dz)  * xm);
            float zp  = mk * x + (1.0f - mk) * (dzp * xlb + (1.0f - dzp) * xm);
            s_u[r][j]       = z;
            s_u[r][128 + j] = zp;
        }
        __syncthreads();

        // ---------- Phase B: ls = u @ Wq^T + bq. k-sliced: thread = (slice s, m).
        // Each Wq element read exactly once per CTA; applied to all 4 rows. ----------
        {
            int s = tid >> 6, m = tid & 63;
            float a0 = 0.f, a1 = 0.f, a2 = 0.f, a3 = 0.f;
            const float* wq = g_WqT + (96 * s) * 64 + m;
            const int kk0 = 96 * s;
#pragma unroll 4
            for (int k = 0; k < 96; k++) {
                float w = __ldg(wq + k * 64);
                a0 = fmaf(s_u[0][kk0 + k], w, a0);
                a1 = fmaf(s_u[1][kk0 + k], w, a1);
                a2 = fmaf(s_u[2][kk0 + k], w, a2);
                a3 = fmaf(s_u[3][kk0 + k], w, a3);
            }
            s_partB[0][m][s] = a0;
            s_partB[1][m][s] = a1;
            s_partB[2][m][s] = a2;
            s_partB[3][m][s] = a3;
        }
        __syncthreads();
        {   // reduce: thread = (r, m)
            int r = tid >> 6, m = tid & 63;
            float4 p = *reinterpret_cast<const float4*>(&s_partB[r][m][0]);
            float v = s_bq[m] + ((p.x + p.y) + (p.z + p.w));
            s_comb2[r][m] = make_float2(v, v);
        }
        __syncthreads();

        // ---------- Phase C: 4 gates with packed f32x2 FMA; thread owns h = tid.
        // float4 (i,f,o,c) loads give (i,f)/(o,c) packed lanes for free. ----------
        unsigned long long acc_if[RPB], acc_oc[RPB];
#pragma unroll
        for (int r = 0; r < RPB; r++) { acc_if[r] = bias_if; acc_oc[r] = bias_oc; }

        ulonglong2 wb[8];
#pragma unroll
        for (int i = 0; i < 8; i++) wb[i] = ldcs_v2(wg + i * 256);

#pragma unroll 1
        for (int k0 = 0; k0 < 320; k0 += 8) {
#pragma unroll
            for (int i = 0; i < 8; i += 2) {
                ulonglong2 w0 = wb[i], w1 = wb[i + 1];
                wb[i]     = ldcs_v2(wg + (k0 + 8 + i) * 256);   // prefetch (padded past 320)
                wb[i + 1] = ldcs_v2(wg + (k0 + 9 + i) * 256);
#pragma unroll
                for (int r = 0; r < RPB; r++) {
                    const ulonglong2 cb =
                        *reinterpret_cast<const ulonglong2*>(&s_comb2[r][k0 + i]);
                    fma2(acc_if[r], w0.x, cb.x);
                    fma2(acc_oc[r], w0.y, cb.x);
                    fma2(acc_if[r], w1.x, cb.y);
                    fma2(acc_oc[r], w1.y, cb.y);
                }
            }
        }

        float hreg[RPB];
#pragma unroll
        for (int r = 0; r < RPB; r++) {
            float ai, afv, ao, ac;
            unpack2(acc_if[r], ai, afv);
            unpack2(acc_oc[r], ao, ac);
            float ig = fast_sigmoid(ai);
            float fg = fast_sigmoid(afv);
            float og = fast_sigmoid(ao);
            float ct = fast_tanh(ac);
            c_reg[r] = fg * c_reg[r] + ig * ct;
            hreg[r]  = og * fast_tanh(c_reg[r]);
        }
        __syncthreads();   // all comb2 reads complete before overwriting h-part
#pragma unroll
        for (int r = 0; r < RPB; r++)
            s_comb2[r][64 + tid] = make_float2(hreg[r], hreg[r]);
        __syncthreads();

        // ---------- Phase E: out = h_new @ Wfc^T + bfc (= x_i for t+1).
        // h-sliced: thread = (slice s2, o). Each Wfc element read once per CTA. ----------
        {
            int s2 = tid >> 7, o = tid & 127;
            float a0 = 0.f, a1 = 0.f, a2 = 0.f, a3 = 0.f;
            const float* wp = g_WfcT + (s2 * 128) * 128 + o;
            const int hh0 = 64 + s2 * 128;
#pragma unroll 4
            for (int h = 0; h < 128; h++) {
                float w = __ldg(wp + h * 128);
                a0 = fmaf(s_comb2[0][hh0 + h].x, w, a0);
                a1 = fmaf(s_comb2[1][hh0 + h].x, w, a1);
                a2 = fmaf(s_comb2[2][hh0 + h].x, w, a2);
                a3 = fmaf(s_comb2[3][hh0 + h].x, w, a3);
            }
            s_partE[0][o][s2] = a0;
            s_partE[1][o][s2] = a1;
            s_partE[2][o][s2] = a2;
            s_partE[3][o][s2] = a3;
        }
        __syncthreads();
        for (int e = tid; e < RPB * 128; e += NTHR) {
            int r = e >> 7, o = e & 127;
            float v = s_bfc[o] + s_partE[r][o][0] + s_partE[r][o][1];
            out[((long)(b0 + r) * Tt + t) * (long)Oo + o] = v;
            s_u[r][256 + o] = v;   // x_i for t+1; disjoint from next Phase A writes
        }
        // no trailing sync: next Phase A writes s_u[0:256) (disjoint threads/addrs);
        // next Phase B reads s_u only after the post-A barrier.
    }
}

extern "C" void kernel_launch(void* const* d_in, const int* in_sizes, int n_in,
                              void* d_out, int out_size)
{
    const float* inp   = (const float*)d_in[0];
    const float* xmean = (const float*)d_in[1];
    const float* Wz    = (const float*)d_in[2];
    const float* bz    = (const float*)d_in[3];
    const float* Wzp   = (const float*)d_in[4];
    const float* bzp   = (const float*)d_in[5];
    const float* Wq    = (const float*)d_in[6];
    const float* bq    = (const float*)d_in[7];
    const float* Wi    = (const float*)d_in[8];
    const float* bi    = (const float*)d_in[9];
    const float* Wf    = (const float*)d_in[10];
    const float* bf    = (const float*)d_in[11];
    const float* Wo    = (const float*)d_in[12];
    const float* bo    = (const float*)d_in[13];
    const float* Wc    = (const float*)d_in[14];
    const float* bc    = (const float*)d_in[15];
    const float* Wfc   = (const float*)d_in[16];
    const float* bfc   = (const float*)d_in[17];
    float* out = (float*)d_out;

    prep_kernel<<<320, 256>>>(Wz, Wzp, Wq, Wi, Wf, Wo, Wc, Wfc);
    lgnet_kernel<<<NBLK, NTHR>>>(inp, xmean, bz, bzp, bq, bi, bf, bo, bc, bfc, out);
}